// round 12
// baseline (speedup 1.0000x reference)
#include <cuda_runtime.h>
#include <cuda_fp16.h>
#include <math.h>
#include <stdint.h>

#define NN 100000
#define CC 128
#define EE 600000
#define HH 64
#define TILE 64
#define NTILES (EE / TILE)      // 9375 exact, no tail
#define MAIN_GRID 304           // 152 SMs * 2 persistent
#define MAIN_THREADS 256

// SMEM byte layout
#define RAW_BUFSZ 34816u        // 4 pairs * 2 tables * 16 rows * 272 B
#define ROWP 272u               // raw row pitch (16B-aligned, conflict-free ldsm)
#define OFF_BP  69632           // 2 raw buffers end; Bp = 16384 B
#define OFF_B1  86016           // 64 floats
#define OFF_W2  86272           // 64 floats
#define OFF_RED 86528           // 8 warps * 16 floats = 512 B
#define SMEM_BYTES 87040        // -> 2 blocks/SM (174 KB)

// Node tables in fp16: v1 = z_out + z_self, v2 = z_in + z_self (25.6 MB each).
__device__ uint4 g_v1h[(size_t)NN * CC / 8];
__device__ uint4 g_v2h[(size_t)NN * CC / 8];

__device__ __forceinline__ uint32_t f2h2(float lo, float hi) {
    uint32_t r;
    asm("cvt.rn.f16x2.f32 %0, %1, %2;" : "=r"(r) : "f"(hi), "f"(lo));
    return r;
}

__global__ void prep_kernel(const float* __restrict__ z_in,
                            const float* __restrict__ z_out,
                            const float* __restrict__ z_self) {
    const int i = blockIdx.x * blockDim.x + threadIdx.x;   // 8 channels / thread
    const float4* zi = (const float4*)z_in;
    const float4* zo = (const float4*)z_out;
    const float4* zs = (const float4*)z_self;
    const float4 s0 = zs[2 * i],     s1 = zs[2 * i + 1];
    const float4 a0 = zo[2 * i],     a1 = zo[2 * i + 1];
    const float4 b0 = zi[2 * i],     b1 = zi[2 * i + 1];
    uint4 o1, o2;
    o1.x = f2h2(a0.x + s0.x, a0.y + s0.y);
    o1.y = f2h2(a0.z + s0.z, a0.w + s0.w);
    o1.z = f2h2(a1.x + s1.x, a1.y + s1.y);
    o1.w = f2h2(a1.z + s1.z, a1.w + s1.w);
    o2.x = f2h2(b0.x + s0.x, b0.y + s0.y);
    o2.y = f2h2(b0.z + s0.z, b0.w + s0.w);
    o2.z = f2h2(b1.x + s1.x, b1.y + s1.y);
    o2.w = f2h2(b1.z + s1.z, b1.w + s1.w);
    g_v1h[i] = o1;
    g_v2h[i] = o2;
}

__device__ __forceinline__ uint32_t smem_u32(const void* p) {
    uint32_t a;
    asm("{ .reg .u64 t; cvta.to.shared.u64 t, %1; cvt.u32.u64 %0, t; }" : "=r"(a) : "l"(p));
    return a;
}
__device__ __forceinline__ void cp16(uint32_t dst, const void* src) {
    asm volatile("cp.async.cg.shared.global [%0], [%1], 16;" :: "r"(dst), "l"(src));
}
__device__ __forceinline__ void mma_f16(float* c,
                                        uint32_t a0, uint32_t a1, uint32_t a2, uint32_t a3,
                                        uint32_t b0, uint32_t b1) {
    asm volatile(
        "mma.sync.aligned.m16n8k16.row.col.f32.f16.f16.f32 "
        "{%0,%1,%2,%3}, {%4,%5,%6,%7}, {%8,%9}, {%0,%1,%2,%3};"
        : "+f"(c[0]), "+f"(c[1]), "+f"(c[2]), "+f"(c[3])
        : "r"(a0), "r"(a1), "r"(a2), "r"(a3), "r"(b0), "r"(b1));
}
__device__ __forceinline__ void ldsm_x4(uint32_t& r0, uint32_t& r1, uint32_t& r2, uint32_t& r3,
                                        uint32_t addr) {
    asm volatile("ldmatrix.sync.aligned.m8n8.x4.shared.b16 {%0,%1,%2,%3}, [%4];"
                 : "=r"(r0), "=r"(r1), "=r"(r2), "=r"(r3) : "r"(addr));
}

// Pipeline: cp.async raw gather of tile t+1 overlaps MMA+epilogue of tile t.
// Warp-pair owns one m16x64 tile (16 edges); product formed on ldmatrix
// fragments (elementwise), so arithmetic matches the LDG->mul->STS path.
__global__ __launch_bounds__(MAIN_THREADS, 2)
void gemm_kernel(const int* __restrict__ eidx,
                 const float* __restrict__ W1,
                 const float* __restrict__ b1,
                 const float* __restrict__ W2,
                 const float* __restrict__ b2,
                 float* __restrict__ out)
{
    extern __shared__ char smem[];
    const uint32_t sb = smem_u32(smem);
    uint4* Bp  = (uint4*)(smem + OFF_BP);
    float* b1s = (float*)(smem + OFF_B1);
    float* w2s = (float*)(smem + OFF_W2);
    float* red = (float*)(smem + OFF_RED);

    const int tid   = threadIdx.x;
    const int lane  = tid & 31;
    const int warp  = tid >> 5;
    const int gid   = lane >> 2;   // 0..7
    const int tig   = lane & 3;    // 0..3
    const int lw    = lane & 15;
    const int hi    = lane >> 4;   // ldsm k-half / table select
    const int pair  = warp >> 1;   // 0..3
    const int nhalf = warp & 1;    // 0 -> cols 0..31, 1 -> 32..63
    const int barid = pair + 1;

    // ---- Stage packed-B frags (fp16) + vectors, once per persistent block ----
    for (int i = tid; i < 8 * 4 * 32; i += MAIN_THREADS) {
        const int l   = i & 31;
        const int nt2 = (i >> 5) & 3;
        const int ks  = i >> 7;
        const int g   = l >> 2;
        const int t   = l & 3;
        const int k0  = ks * 16;
        const int n0  = nt2 * 16 + g;
        const int n1  = n0 + 8;
        uint4 v;
        v.x = f2h2(W1[(k0 + 2 * t) * HH + n0],     W1[(k0 + 2 * t + 1) * HH + n0]);
        v.y = f2h2(W1[(k0 + 2 * t + 8) * HH + n0], W1[(k0 + 2 * t + 9) * HH + n0]);
        v.z = f2h2(W1[(k0 + 2 * t) * HH + n1],     W1[(k0 + 2 * t + 1) * HH + n1]);
        v.w = f2h2(W1[(k0 + 2 * t + 8) * HH + n1], W1[(k0 + 2 * t + 9) * HH + n1]);
        Bp[i] = v;
    }
    if (tid < HH) { b1s[tid] = b1[tid]; w2s[tid] = W2[tid]; }
    const float b2v = b2[0];
    __syncthreads();

    const int* srcI = eidx;
    const int* dstI = eidx + EE;
    const char* t1b = (const char*)g_v1h;
    const char* t2b = (const char*)g_v2h;

    // Per-lane gather dst constant: pair block + table + warp-half rows + chunk
    const uint32_t gdst0 = sb + (uint32_t)pair * 8704u + (uint32_t)(lane >> 4) * 4352u
                         + (uint32_t)(warp & 1) * (8u * ROWP) + (uint32_t)lw * 16u;
    const char* gtab = hi ? t2b : t1b;   // lanes 0-15: v1 chunks, 16-31: v2 chunks
    const unsigned lby = (unsigned)lw * 16u;

    // ldsm base (k-chunk 0) for this warp's pair tile, buffer 0
    const uint32_t la0 = sb + (uint32_t)pair * 8704u + (uint32_t)lw * ROWP + (uint32_t)hi * 16u;

    // ---- gather issue: 8 cp.async per lane (edges 8*warp..+7 of tile nt) ----
    auto gather_issue = [&](int nt, uint32_t bufOff) {
        if (nt < NTILES) {
            const int eI = nt * TILE + warp * 8 + (lane & 7);
            const unsigned myOff =
                (unsigned)((((lane >> 3) & 1) ? dstI : srcI)[eI]) * 256u;
            const uint32_t d0 = gdst0 + bufOff;
            #pragma unroll
            for (int i = 0; i < 8; i++) {
                const unsigned so = __shfl_sync(0xffffffffu, myOff, i);
                const unsigned dofs = __shfl_sync(0xffffffffu, myOff, 8 + i);
                const unsigned g = hi ? dofs : so;
                cp16(d0 + (uint32_t)i * ROWP, gtab + g + lby);
            }
        }
        asm volatile("cp.async.commit_group;" ::: "memory");
    };

    // ---- Prologue: fill buffer 0 for the first tile ----
    gather_issue(blockIdx.x, 0u);

    uint32_t p = 0;
    for (int tile = blockIdx.x; tile < NTILES; tile += MAIN_GRID) {
        // Issue next tile into the other buffer (overlaps this tile's compute)
        gather_issue(tile + MAIN_GRID, (p ^ 1u) ? RAW_BUFSZ : 0u);
        asm volatile("cp.async.wait_group 1;" ::: "memory");
        asm volatile("bar.sync %0, %1;" :: "r"(barid), "r"(64) : "memory");

        // ---- Consume buffer p: dual ldsm -> product frags -> mma ----
        const uint32_t v1la = la0 + (p ? RAW_BUFSZ : 0u);
        const uint32_t v2la = v1la + 4352u;

        float acc[4][4];
        #pragma unroll
        for (int jj = 0; jj < 4; jj++)
            #pragma unroll
            for (int c = 0; c < 4; c++) acc[jj][c] = 0.f;

        #pragma unroll
        for (int ks = 0; ks < 8; ks++) {
            uint32_t x0, x1, x2, x3, y0, y1, y2, y3;
            ldsm_x4(x0, x1, x2, x3, v1la + (uint32_t)(ks * 32));
            ldsm_x4(y0, y1, y2, y3, v2la + (uint32_t)(ks * 32));
            uint32_t a0, a1, a2, a3;
            asm("mul.rn.f16x2 %0, %1, %2;" : "=r"(a0) : "r"(x0), "r"(y0));
            asm("mul.rn.f16x2 %0, %1, %2;" : "=r"(a1) : "r"(x1), "r"(y1));
            asm("mul.rn.f16x2 %0, %1, %2;" : "=r"(a2) : "r"(x2), "r"(y2));
            asm("mul.rn.f16x2 %0, %1, %2;" : "=r"(a3) : "r"(x3), "r"(y3));
            const uint4 bf0 = Bp[(ks * 4 + 2 * nhalf) * 32 + lane];
            const uint4 bf1 = Bp[(ks * 4 + 2 * nhalf + 1) * 32 + lane];
            mma_f16(acc[0], a0, a1, a2, a3, bf0.x, bf0.y);
            mma_f16(acc[1], a0, a1, a2, a3, bf0.z, bf0.w);
            mma_f16(acc[2], a0, a1, a2, a3, bf1.x, bf1.y);
            mma_f16(acc[3], a0, a1, a2, a3, bf1.z, bf1.w);
        }

        // ---- Epilogue: bias + ELU + dot(W2) over this warp's 32 n's ----
        float p0 = 0.f, p1 = 0.f;
        #pragma unroll
        for (int jj = 0; jj < 4; jj++) {
            const int n = (nhalf * 4 + jj) * 8 + 2 * tig;
            const float bb0 = b1s[n], bb1 = b1s[n + 1];
            const float ww0 = w2s[n], ww1 = w2s[n + 1];
            float x;
            x = acc[jj][0] + bb0; p0 = fmaf(x > 0.f ? x : (__expf(x) - 1.f), ww0, p0);
            x = acc[jj][1] + bb1; p0 = fmaf(x > 0.f ? x : (__expf(x) - 1.f), ww1, p0);
            x = acc[jj][2] + bb0; p1 = fmaf(x > 0.f ? x : (__expf(x) - 1.f), ww0, p1);
            x = acc[jj][3] + bb1; p1 = fmaf(x > 0.f ? x : (__expf(x) - 1.f), ww1, p1);
        }
        p0 += __shfl_xor_sync(0xffffffffu, p0, 1);
        p0 += __shfl_xor_sync(0xffffffffu, p0, 2);
        p1 += __shfl_xor_sync(0xffffffffu, p1, 1);
        p1 += __shfl_xor_sync(0xffffffffu, p1, 2);
        if (tig == 0) {
            red[warp * 16 + gid]     = p0;
            red[warp * 16 + 8 + gid] = p1;
        }
        asm volatile("bar.sync %0, %1;" :: "r"(barid), "r"(64) : "memory");
        // ^ also orders: both warps done reading buf p before next iter refills it

        // ---- Finalize: pair's 16 edges, 8 per warp ----
        if (lane < 8) {
            const int el = nhalf * 8 + lane;
            const float s = red[(pair * 2) * 16 + el] + red[(pair * 2 + 1) * 16 + el] + b2v;
            out[tile * TILE + pair * 16 + el] = 1.0f / (1.0f + __expf(-s));
        }
        p ^= 1u;
    }
}

extern "C" void kernel_launch(void* const* d_in, const int* in_sizes, int n_in,
                              void* d_out, int out_size) {
    const float* z_in   = (const float*)d_in[0];
    const float* z_out  = (const float*)d_in[1];
    const float* z_self = (const float*)d_in[2];
    const int*   eidx   = (const int*)d_in[3];
    const float* W1     = (const float*)d_in[4];
    const float* b1     = (const float*)d_in[5];
    const float* W2     = (const float*)d_in[6];
    const float* b2     = (const float*)d_in[7];
    float*       outp   = (float*)d_out;

    prep_kernel<<<NN * CC / 8 / 256, 256>>>(z_in, z_out, z_self);

    cudaFuncSetAttribute(gemm_kernel,
                         cudaFuncAttributeMaxDynamicSharedMemorySize, SMEM_BYTES);
    gemm_kernel<<<MAIN_GRID, MAIN_THREADS, SMEM_BYTES>>>(eidx, W1, b1, W2, b2, outp);
}

// round 13
// speedup vs baseline: 1.2602x; 1.2602x over previous
#include <cuda_runtime.h>
#include <cuda_fp16.h>
#include <math.h>
#include <stdint.h>

#define NN 100000
#define CC 128
#define EE 600000
#define HH 64
#define TILE 128
#define NTILES ((EE + TILE - 1) / TILE)   // 4688 (last tile half)
#define MAIN_GRID 608                      // 152 SMs * 4 persistent
#define MAIN_THREADS 256

#define APW 68                  // A pitch in 32-bit words (fp16x2 units): 64 + 4 pad

// SMEM float offsets
#define OFF_A   0               // 128*68 = 8704 words
#define OFF_BP  8704            // packed B frags: 8*4*32 uint4 = 4096 words
#define OFF_B1  12800           // 64
#define OFF_W2  12864           // 64
#define SMEM_FLOATS 12928       // 51712 bytes -> 4 blocks/SM (207KB)

// Node tables in fp16: v1 = z_out + z_self, v2 = z_in + z_self (25.6 MB each).
__device__ uint4 g_v1h[(size_t)NN * CC / 8];
__device__ uint4 g_v2h[(size_t)NN * CC / 8];

__device__ __forceinline__ uint32_t f2h2(float lo, float hi) {
    uint32_t r;
    asm("cvt.rn.f16x2.f32 %0, %1, %2;" : "=r"(r) : "f"(hi), "f"(lo));
    return r;
}

__global__ void prep_kernel(const float* __restrict__ z_in,
                            const float* __restrict__ z_out,
                            const float* __restrict__ z_self) {
    const int i = blockIdx.x * blockDim.x + threadIdx.x;   // 8 channels / thread
    const float4* zi = (const float4*)z_in;
    const float4* zo = (const float4*)z_out;
    const float4* zs = (const float4*)z_self;
    const float4 s0 = zs[2 * i],     s1 = zs[2 * i + 1];
    const float4 a0 = zo[2 * i],     a1 = zo[2 * i + 1];
    const float4 b0 = zi[2 * i],     b1 = zi[2 * i + 1];
    uint4 o1, o2;
    o1.x = f2h2(a0.x + s0.x, a0.y + s0.y);
    o1.y = f2h2(a0.z + s0.z, a0.w + s0.w);
    o1.z = f2h2(a1.x + s1.x, a1.y + s1.y);
    o1.w = f2h2(a1.z + s1.z, a1.w + s1.w);
    o2.x = f2h2(b0.x + s0.x, b0.y + s0.y);
    o2.y = f2h2(b0.z + s0.z, b0.w + s0.w);
    o2.z = f2h2(b1.x + s1.x, b1.y + s1.y);
    o2.w = f2h2(b1.z + s1.z, b1.w + s1.w);
    g_v1h[i] = o1;
    g_v2h[i] = o2;
}

__device__ __forceinline__ void mma_f16(float* c,
                                        uint32_t a0, uint32_t a1, uint32_t a2, uint32_t a3,
                                        uint32_t b0, uint32_t b1) {
    asm volatile(
        "mma.sync.aligned.m16n8k16.row.col.f32.f16.f16.f32 "
        "{%0,%1,%2,%3}, {%4,%5,%6,%7}, {%8,%9}, {%0,%1,%2,%3};"
        : "+f"(c[0]), "+f"(c[1]), "+f"(c[2]), "+f"(c[3])
        : "r"(a0), "r"(a1), "r"(a2), "r"(a3), "r"(b0), "r"(b1));
}

// Fused gather + GEMM (fp16 mma.sync) + ELU + GEMV + sigmoid.
// Warp owns 16 edges and all 64 N-columns: ZERO block/pair barriers in the
// tile loop (only __syncwarp), so each warp free-runs and its next-tile
// gather LDGs overlap its own epilogue. Gather is exchange-free LDG.64.
__global__ __launch_bounds__(MAIN_THREADS, 4)
void gemm_kernel(const int* __restrict__ eidx,
                 const float* __restrict__ W1,
                 const float* __restrict__ b1,
                 const float* __restrict__ W2,
                 const float* __restrict__ b2,
                 float* __restrict__ out)
{
    extern __shared__ float smem[];
    uint32_t* Au  = (uint32_t*)(smem + OFF_A);
    uint4*    Bp  = (uint4*)(smem + OFF_BP);
    float*    b1s = smem + OFF_B1;
    float*    w2s = smem + OFF_W2;

    const int tid  = threadIdx.x;
    const int lane = tid & 31;
    const int warp = tid >> 5;
    const int gid  = lane >> 2;   // 0..7
    const int tig  = lane & 3;    // 0..3
    const int wb   = warp * 16;   // A-row base for this warp
    const int lw   = lane & 15;

    // ---- Stage packed-B frags (fp16) + vectors, once per persistent block ----
    for (int i = tid; i < 8 * 4 * 32; i += MAIN_THREADS) {
        const int l   = i & 31;
        const int nt2 = (i >> 5) & 3;
        const int ks  = i >> 7;
        const int g   = l >> 2;
        const int t   = l & 3;
        const int k0  = ks * 16;
        const int n0  = nt2 * 16 + g;
        const int n1  = n0 + 8;
        uint4 v;
        v.x = f2h2(W1[(k0 + 2 * t) * HH + n0],     W1[(k0 + 2 * t + 1) * HH + n0]);
        v.y = f2h2(W1[(k0 + 2 * t + 8) * HH + n0], W1[(k0 + 2 * t + 9) * HH + n0]);
        v.z = f2h2(W1[(k0 + 2 * t) * HH + n1],     W1[(k0 + 2 * t + 1) * HH + n1]);
        v.w = f2h2(W1[(k0 + 2 * t + 8) * HH + n1], W1[(k0 + 2 * t + 9) * HH + n1]);
        Bp[i] = v;
    }
    if (tid < HH) { b1s[tid] = b1[tid]; w2s[tid] = W2[tid]; }
    const float b2v = b2[0];
    __syncthreads();

    const int* srcI = eidx;
    const int* dstI = eidx + EE;
    const char* t1b = (const char*)g_v1h;
    const char* t2b = (const char*)g_v2h;
    const unsigned laneOff = (unsigned)lane * 8u;

    for (int tile = blockIdx.x; tile < NTILES; tile += MAIN_GRID) {
        const int e0 = tile * TILE;

        // ---- Gather own 16 edges into As rows [wb, wb+16) (exchange-free) ----
        {
            int eS = e0 + wb + lw;
            if (eS >= EE) eS = EE - 1;            // tail: duplicate, discarded
            const unsigned myOff =
                (unsigned)((lane < 16) ? srcI[eS] : dstI[eS]) * 256u;
            #pragma unroll
            for (int i = 0; i < 16; i++) {
                const unsigned so = __shfl_sync(0xffffffffu, myOff, i);
                const unsigned dofs = __shfl_sync(0xffffffffu, myOff, 16 + i);
                const uint2 a = *(const uint2*)(t1b + so + laneOff);
                const uint2 b = *(const uint2*)(t2b + dofs + laneOff);
                uint2 p;
                asm("mul.rn.f16x2 %0, %1, %2;" : "=r"(p.x) : "r"(a.x), "r"(b.x));
                asm("mul.rn.f16x2 %0, %1, %2;" : "=r"(p.y) : "r"(a.y), "r"(b.y));
                *(uint2*)(Au + (wb + i) * APW + lane * 2) = p;   // STS.64
            }
        }
        __syncwarp();   // STS visible to all lanes' LDS below

        // ---- GEMM: D[16x64] = A[16x128] x B[128x64], k16 steps ----
        float acc[8][4];
        #pragma unroll
        for (int nt = 0; nt < 8; nt++)
            #pragma unroll
            for (int c = 0; c < 4; c++) acc[nt][c] = 0.f;

        #pragma unroll
        for (int ks = 0; ks < 8; ks++) {
            const uint32_t* ar = Au + (wb + gid) * APW + 8 * ks + tig;
            const uint32_t a0 = ar[0];            // row gid,   k lo pair
            const uint32_t a2 = ar[4];            // row gid,   k hi pair
            const uint32_t a1 = ar[8 * APW];      // row gid+8, k lo pair
            const uint32_t a3 = ar[8 * APW + 4];  // row gid+8, k hi pair
            #pragma unroll
            for (int nt2 = 0; nt2 < 4; nt2++) {
                const uint4 bf = Bp[(ks * 4 + nt2) * 32 + lane];
                mma_f16(acc[2 * nt2],     a0, a1, a2, a3, bf.x, bf.y);
                mma_f16(acc[2 * nt2 + 1], a0, a1, a2, a3, bf.z, bf.w);
            }
        }
        __syncwarp();   // all lanes' A-LDS done before next tile's STS rewrite

        // ---- Epilogue: bias + ELU + dot(W2), 4-lane shfl reduce, sigmoid ----
        float p0 = 0.f, p1 = 0.f;
        #pragma unroll
        for (int nt = 0; nt < 8; nt++) {
            const int n = nt * 8 + 2 * tig;
            const float bb0 = b1s[n], bb1 = b1s[n + 1];
            const float ww0 = w2s[n], ww1 = w2s[n + 1];
            float x;
            x = acc[nt][0] + bb0; p0 = fmaf(x > 0.f ? x : (__expf(x) - 1.f), ww0, p0);
            x = acc[nt][1] + bb1; p0 = fmaf(x > 0.f ? x : (__expf(x) - 1.f), ww1, p0);
            x = acc[nt][2] + bb0; p1 = fmaf(x > 0.f ? x : (__expf(x) - 1.f), ww0, p1);
            x = acc[nt][3] + bb1; p1 = fmaf(x > 0.f ? x : (__expf(x) - 1.f), ww1, p1);
        }
        p0 += __shfl_xor_sync(0xffffffffu, p0, 1);
        p0 += __shfl_xor_sync(0xffffffffu, p0, 2);
        p1 += __shfl_xor_sync(0xffffffffu, p1, 1);
        p1 += __shfl_xor_sync(0xffffffffu, p1, 2);
        if (tig == 0) {
            const int eo = e0 + wb + gid;
            if (eo < EE)     out[eo]     = 1.0f / (1.0f + __expf(-(p0 + b2v)));
            if (eo + 8 < EE) out[eo + 8] = 1.0f / (1.0f + __expf(-(p1 + b2v)));
        }
    }
}

extern "C" void kernel_launch(void* const* d_in, const int* in_sizes, int n_in,
                              void* d_out, int out_size) {
    const float* z_in   = (const float*)d_in[0];
    const float* z_out  = (const float*)d_in[1];
    const float* z_self = (const float*)d_in[2];
    const int*   eidx   = (const int*)d_in[3];
    const float* W1     = (const float*)d_in[4];
    const float* b1     = (const float*)d_in[5];
    const float* W2     = (const float*)d_in[6];
    const float* b2     = (const float*)d_in[7];
    float*       outp   = (float*)d_out;

    prep_kernel<<<NN * CC / 8 / 256, 256>>>(z_in, z_out, z_self);

    const int smem_bytes = SMEM_FLOATS * (int)sizeof(float);   // 51712
    cudaFuncSetAttribute(gemm_kernel,
                         cudaFuncAttributeMaxDynamicSharedMemorySize, smem_bytes);
    gemm_kernel<<<MAIN_GRID, MAIN_THREADS, smem_bytes>>>(eidx, W1, b1, W2, b2, outp);
}

// round 14
// speedup vs baseline: 1.2894x; 1.0231x over previous
#include <cuda_runtime.h>
#include <cuda_fp16.h>
#include <math.h>
#include <stdint.h>

#define NN 100000
#define CC 128
#define EE 600000
#define HH 64
#define NUNITS (EE / 16)        // 37500 16-edge warp units, exact
#define MAIN_GRID 608           // 152 SMs * 4 persistent
#define MAIN_THREADS 256
#define NWARPS_TOTAL (MAIN_GRID * (MAIN_THREADS / 32))   // 4864

#define APW 68                  // A pitch in 32-bit words (fp16x2 units): 64 + 4 pad

// SMEM float offsets
#define OFF_A   0               // 128*68 = 8704 words
#define OFF_BP  8704            // packed B frags: 8*4*32 uint4 = 4096 words
#define OFF_B1  12800           // 64
#define OFF_W2  12864           // 64
#define SMEM_FLOATS 12928       // 51712 bytes -> 4 blocks/SM (207KB)

// Node tables in fp16: v1 = z_out + z_self, v2 = z_in + z_self (25.6 MB each).
__device__ uint4 g_v1h[(size_t)NN * CC / 8];
__device__ uint4 g_v2h[(size_t)NN * CC / 8];
__device__ unsigned int g_unit_ctr;   // reset by prep_kernel each launch

__device__ __forceinline__ uint32_t f2h2(float lo, float hi) {
    uint32_t r;
    asm("cvt.rn.f16x2.f32 %0, %1, %2;" : "=r"(r) : "f"(hi), "f"(lo));
    return r;
}

__global__ void prep_kernel(const float* __restrict__ z_in,
                            const float* __restrict__ z_out,
                            const float* __restrict__ z_self) {
    const int i = blockIdx.x * blockDim.x + threadIdx.x;   // 8 channels / thread
    if (i == 0) g_unit_ctr = NWARPS_TOTAL;                 // reset stealing ctr
    const float4* zi = (const float4*)z_in;
    const float4* zo = (const float4*)z_out;
    const float4* zs = (const float4*)z_self;
    const float4 s0 = zs[2 * i],     s1 = zs[2 * i + 1];
    const float4 a0 = zo[2 * i],     a1 = zo[2 * i + 1];
    const float4 b0 = zi[2 * i],     b1 = zi[2 * i + 1];
    uint4 o1, o2;
    o1.x = f2h2(a0.x + s0.x, a0.y + s0.y);
    o1.y = f2h2(a0.z + s0.z, a0.w + s0.w);
    o1.z = f2h2(a1.x + s1.x, a1.y + s1.y);
    o1.w = f2h2(a1.z + s1.z, a1.w + s1.w);
    o2.x = f2h2(b0.x + s0.x, b0.y + s0.y);
    o2.y = f2h2(b0.z + s0.z, b0.w + s0.w);
    o2.z = f2h2(b1.x + s1.x, b1.y + s1.y);
    o2.w = f2h2(b1.z + s1.z, b1.w + s1.w);
    g_v1h[i] = o1;
    g_v2h[i] = o2;
}

__device__ __forceinline__ void mma_f16(float* c,
                                        uint32_t a0, uint32_t a1, uint32_t a2, uint32_t a3,
                                        uint32_t b0, uint32_t b1) {
    asm volatile(
        "mma.sync.aligned.m16n8k16.row.col.f32.f16.f16.f32 "
        "{%0,%1,%2,%3}, {%4,%5,%6,%7}, {%8,%9}, {%0,%1,%2,%3};"
        : "+f"(c[0]), "+f"(c[1]), "+f"(c[2]), "+f"(c[3])
        : "r"(a0), "r"(a1), "r"(a2), "r"(a3), "r"(b0), "r"(b1));
}

// Fused gather + GEMM (fp16 mma.sync) + ELU + GEMV + sigmoid.
// Warp owns its 16 As rows permanently; 16-edge work units are claimed via a
// per-warp atomic counter (near-perfect balance, zero block barriers in loop).
__global__ __launch_bounds__(MAIN_THREADS, 4)
void gemm_kernel(const int* __restrict__ eidx,
                 const float* __restrict__ W1,
                 const float* __restrict__ b1,
                 const float* __restrict__ W2,
                 const float* __restrict__ b2,
                 float* __restrict__ out)
{
    extern __shared__ float smem[];
    uint32_t* Au  = (uint32_t*)(smem + OFF_A);
    uint4*    Bp  = (uint4*)(smem + OFF_BP);
    float*    b1s = smem + OFF_B1;
    float*    w2s = smem + OFF_W2;

    const int tid  = threadIdx.x;
    const int lane = tid & 31;
    const int warp = tid >> 5;
    const int gid  = lane >> 2;   // 0..7
    const int tig  = lane & 3;    // 0..3
    const int wb   = warp * 16;   // A-row base for this warp (fixed)
    const int lw   = lane & 15;

    // ---- Stage packed-B frags (fp16) + vectors, once per persistent block ----
    for (int i = tid; i < 8 * 4 * 32; i += MAIN_THREADS) {
        const int l   = i & 31;
        const int nt2 = (i >> 5) & 3;
        const int ks  = i >> 7;
        const int g   = l >> 2;
        const int t   = l & 3;
        const int k0  = ks * 16;
        const int n0  = nt2 * 16 + g;
        const int n1  = n0 + 8;
        uint4 v;
        v.x = f2h2(W1[(k0 + 2 * t) * HH + n0],     W1[(k0 + 2 * t + 1) * HH + n0]);
        v.y = f2h2(W1[(k0 + 2 * t + 8) * HH + n0], W1[(k0 + 2 * t + 9) * HH + n0]);
        v.z = f2h2(W1[(k0 + 2 * t) * HH + n1],     W1[(k0 + 2 * t + 1) * HH + n1]);
        v.w = f2h2(W1[(k0 + 2 * t + 8) * HH + n1], W1[(k0 + 2 * t + 9) * HH + n1]);
        Bp[i] = v;
    }
    if (tid < HH) { b1s[tid] = b1[tid]; w2s[tid] = W2[tid]; }
    const float b2v = b2[0];
    __syncthreads();

    const int* srcI = eidx;
    const int* dstI = eidx + EE;
    const char* t1b = (const char*)g_v1h;
    const char* t2b = (const char*)g_v2h;
    const unsigned laneOff = (unsigned)lane * 8u;

    int unit = blockIdx.x * (MAIN_THREADS / 32) + warp;   // initial assignment

    while (unit < NUNITS) {
        // Steal next unit early; latency hidden behind this unit's work.
        int nxt;
        if (lane == 0) nxt = (int)atomicAdd(&g_unit_ctr, 1u);
        nxt = __shfl_sync(0xffffffffu, nxt, 0);

        const int e0 = unit * 16;

        // ---- Gather 16 edges into As rows [wb, wb+16), 4-edge batches ----
        {
            const unsigned myOff =
                (unsigned)((lane < 16) ? srcI[e0 + lw] : dstI[e0 + lw]) * 256u;
            #pragma unroll
            for (int b = 0; b < 4; b++) {
                uint2 va[4], vb[4];
                #pragma unroll
                for (int j = 0; j < 4; j++) {
                    const int i = b * 4 + j;
                    const unsigned so = __shfl_sync(0xffffffffu, myOff, i);
                    const unsigned dofs = __shfl_sync(0xffffffffu, myOff, 16 + i);
                    va[j] = *(const uint2*)(t1b + so + laneOff);
                    vb[j] = *(const uint2*)(t2b + dofs + laneOff);
                }
                #pragma unroll
                for (int j = 0; j < 4; j++) {
                    const int i = b * 4 + j;
                    uint2 p;
                    asm("mul.rn.f16x2 %0, %1, %2;" : "=r"(p.x) : "r"(va[j].x), "r"(vb[j].x));
                    asm("mul.rn.f16x2 %0, %1, %2;" : "=r"(p.y) : "r"(va[j].y), "r"(vb[j].y));
                    *(uint2*)(Au + (wb + i) * APW + lane * 2) = p;   // STS.64
                }
            }
        }
        __syncwarp();   // STS visible to all lanes' LDS below

        // ---- GEMM: D[16x64] = A[16x128] x B[128x64], k16 steps ----
        float acc[8][4];
        #pragma unroll
        for (int nt = 0; nt < 8; nt++)
            #pragma unroll
            for (int c = 0; c < 4; c++) acc[nt][c] = 0.f;

        #pragma unroll
        for (int ks = 0; ks < 8; ks++) {
            const uint32_t* ar = Au + (wb + gid) * APW + 8 * ks + tig;
            const uint32_t a0 = ar[0];            // row gid,   k lo pair
            const uint32_t a2 = ar[4];            // row gid,   k hi pair
            const uint32_t a1 = ar[8 * APW];      // row gid+8, k lo pair
            const uint32_t a3 = ar[8 * APW + 4];  // row gid+8, k hi pair
            #pragma unroll
            for (int nt2 = 0; nt2 < 4; nt2++) {
                const uint4 bf = Bp[(ks * 4 + nt2) * 32 + lane];
                mma_f16(acc[2 * nt2],     a0, a1, a2, a3, bf.x, bf.y);
                mma_f16(acc[2 * nt2 + 1], a0, a1, a2, a3, bf.z, bf.w);
            }
        }
        __syncwarp();   // all lanes' A-LDS done before next unit's STS rewrite

        // ---- Epilogue: bias + ELU + dot(W2), 4-lane shfl reduce, sigmoid ----
        float p0 = 0.f, p1 = 0.f;
        #pragma unroll
        for (int nt = 0; nt < 8; nt++) {
            const int n = nt * 8 + 2 * tig;
            const float2 bb = *(const float2*)(b1s + n);   // LDS.64
            const float2 ww = *(const float2*)(w2s + n);   // LDS.64
            float x;
            x = acc[nt][0] + bb.x; p0 = fmaf(x > 0.f ? x : (__expf(x) - 1.f), ww.x, p0);
            x = acc[nt][1] + bb.y; p0 = fmaf(x > 0.f ? x : (__expf(x) - 1.f), ww.y, p0);
            x = acc[nt][2] + bb.x; p1 = fmaf(x > 0.f ? x : (__expf(x) - 1.f), ww.x, p1);
            x = acc[nt][3] + bb.y; p1 = fmaf(x > 0.f ? x : (__expf(x) - 1.f), ww.y, p1);
        }
        p0 += __shfl_xor_sync(0xffffffffu, p0, 1);
        p0 += __shfl_xor_sync(0xffffffffu, p0, 2);
        p1 += __shfl_xor_sync(0xffffffffu, p1, 1);
        p1 += __shfl_xor_sync(0xffffffffu, p1, 2);
        if (tig == 0) {
            out[e0 + gid]     = 1.0f / (1.0f + __expf(-(p0 + b2v)));
            out[e0 + gid + 8] = 1.0f / (1.0f + __expf(-(p1 + b2v)));
        }

        unit = nxt;
    }
}

extern "C" void kernel_launch(void* const* d_in, const int* in_sizes, int n_in,
                              void* d_out, int out_size) {
    const float* z_in   = (const float*)d_in[0];
    const float* z_out  = (const float*)d_in[1];
    const float* z_self = (const float*)d_in[2];
    const int*   eidx   = (const int*)d_in[3];
    const float* W1     = (const float*)d_in[4];
    const float* b1     = (const float*)d_in[5];
    const float* W2     = (const float*)d_in[6];
    const float* b2     = (const float*)d_in[7];
    float*       outp   = (float*)d_out;

    prep_kernel<<<NN * CC / 8 / 256, 256>>>(z_in, z_out, z_self);

    const int smem_bytes = SMEM_FLOATS * (int)sizeof(float);   // 51712
    cudaFuncSetAttribute(gemm_kernel,
                         cudaFuncAttributeMaxDynamicSharedMemorySize, smem_bytes);
    gemm_kernel<<<MAIN_GRID, MAIN_THREADS, smem_bytes>>>(eidx, W1, b1, W2, b2, outp);
}